// round 7
// baseline (speedup 1.0000x reference)
#include <cuda_runtime.h>
#include <math_constants.h>
#include <cstdint>

#define NGROUPS 4096
#define NPAIRS  2048
#define DIM     64
#define MM      128
#define PSTR    68    // stride for 64-wide tiles
#define WSTR    72    // weight stride (conflict-free B frags)
#define SSTR    132   // stride for 128-wide sim tile
#define NTHREADS 512

// ---- smem layout (float offsets) ----
#define OFF_P1   0        // p1: 128x64 @68
#define OFF_P2   8704     // p2
#define OFF_H1   17408    // h1 (phase A) / sim 128x128@132 (phase B overlay)
#define OFF_H2   26112    // h2
#define OFF_SIM  17408
#define OFF_T1   34816    // t1
#define OFF_T2   43520    // t2
#define OFF_W    52224    // 64x72 weights (W1 then W2)
#define OFF_STAT 56832    // rowmax,rowinv,colmax,colinv,am,bn (128 ea), b1,b2 (64 ea)
#define SMEM_FLOATS 57728
#define SMEM_BYTES  (SMEM_FLOATS * 4)

__device__ int g_off[NGROUPS];
__device__ int g_size[NGROUPS];

__global__ void scan_kernel(const int* __restrict__ raw) {
    __shared__ int wsum[32];
    const int stride =
        (raw[1] == 0 && raw[3] == 0 && raw[5] == 0 && raw[7] == 0) ? 2 : 1;
    int tid = threadIdx.x;
    int base = tid * 4;
    int v[4]; int s = 0;
#pragma unroll
    for (int i = 0; i < 4; i++) { v[i] = s; s += raw[(base + i) * stride]; }
    int lane = tid & 31, w = tid >> 5;
    int x = s;
#pragma unroll
    for (int d = 1; d < 32; d <<= 1) { int y = __shfl_up_sync(0xffffffffu, x, d); if (lane >= d) x += y; }
    if (lane == 31) wsum[w] = x;
    int excl = x - s;
    __syncthreads();
    if (w == 0) {
        int ws = wsum[lane]; int xx = ws;
#pragma unroll
        for (int d = 1; d < 32; d <<= 1) { int y = __shfl_up_sync(0xffffffffu, xx, d); if (lane >= d) xx += y; }
        wsum[lane] = xx - ws;
    }
    __syncthreads();
    int off = wsum[w] + excl;
#pragma unroll
    for (int i = 0; i < 4; i++) {
        g_off[base + i]  = off + v[i];
        g_size[base + i] = raw[(base + i) * stride];
    }
}

// ---- tf32 helpers ----
__device__ __forceinline__ void split_tf32(float x, uint32_t& hi, uint32_t& lo) {
    uint32_t h;
    asm("cvt.rna.tf32.f32 %0, %1;" : "=r"(h) : "f"(x));
    float r = x - __uint_as_float(h);
    asm("cvt.rna.tf32.f32 %0, %1;" : "=r"(lo) : "f"(r));
    hi = h;
}

__device__ __forceinline__ void mma8(float* c, const uint32_t* a, const uint32_t* b) {
    asm volatile("mma.sync.aligned.m16n8k8.row.col.f32.tf32.tf32.f32 "
        "{%0,%1,%2,%3},{%4,%5,%6,%7},{%8,%9},{%0,%1,%2,%3};"
        : "+f"(c[0]), "+f"(c[1]), "+f"(c[2]), "+f"(c[3])
        : "r"(a[0]), "r"(a[1]), "r"(a[2]), "r"(a[3]), "r"(b[0]), "r"(b[1]));
}

// 16xN warp tile (N = 64 = 8 n-frags), 3xtf32 compensated.
// A element (r,c) at aB[r*ASR + c*ASC]; B element (k,n) at bB[k*BSK + n*BSN].
// acc layout per frag: c0,c1 = row g cols 2t,2t+1; c2,c3 = row g+8.
template<bool USE_AM>
__device__ __forceinline__ void warp_gemm(
    float acc[8][4],
    const float* __restrict__ aB, int ASR, int ASC, int r0,
    const float* __restrict__ bB, int BSK, int BSN, int nbase,
    int ksteps, int g, int t, const float* __restrict__ amv)
{
    for (int k8 = 0; k8 < ksteps; k8++) {
        int k0 = k8 << 3;
        float a0 = aB[(r0 + g) * ASR + (k0 + t) * ASC];
        float a1 = aB[(r0 + g + 8) * ASR + (k0 + t) * ASC];
        float a2 = aB[(r0 + g) * ASR + (k0 + t + 4) * ASC];
        float a3 = aB[(r0 + g + 8) * ASR + (k0 + t + 4) * ASC];
        if (USE_AM) {
            float w0 = amv[k0 + t], w1 = amv[k0 + t + 4];
            a0 *= w0; a1 *= w0; a2 *= w1; a3 *= w1;
        }
        uint32_t ah[4], al[4];
        split_tf32(a0, ah[0], al[0]);
        split_tf32(a1, ah[1], al[1]);
        split_tf32(a2, ah[2], al[2]);
        split_tf32(a3, ah[3], al[3]);
#pragma unroll
        for (int n8 = 0; n8 < 8; n8++) {
            int nc = nbase + (n8 << 3) + g;
            float b0 = bB[(k0 + t) * BSK + nc * BSN];
            float b1 = bB[(k0 + t + 4) * BSK + nc * BSN];
            uint32_t bh[2], bl[2];
            split_tf32(b0, bh[0], bl[0]);
            split_tf32(b1, bh[1], bl[1]);
            mma8(acc[n8], ah, bh);
            mma8(acc[n8], al, bh);
            mma8(acc[n8], ah, bl);
        }
    }
}

__global__ __launch_bounds__(NTHREADS) void cross_kernel(
    const float* __restrict__ data, const float* __restrict__ W1g,
    const float* __restrict__ b1g, const float* __restrict__ W2g,
    const float* __restrict__ b2g,
    float* __restrict__ res_out, float* __restrict__ s1_out, float* __restrict__ s2_out)
{
    extern __shared__ float smf[];
    float* p1   = smf + OFF_P1;
    float* p2   = smf + OFF_P2;
    float* simb = smf + OFF_SIM;
    float* t1   = smf + OFF_T1;
    float* t2   = smf + OFF_T2;
    float* Ws   = smf + OFF_W;
    float* rowmax = smf + OFF_STAT;
    float* rowinv = smf + OFF_STAT + 128;
    float* colmax = smf + OFF_STAT + 256;
    float* colinv = smf + OFF_STAT + 384;
    float* am     = smf + OFF_STAT + 512;
    float* bn     = smf + OFF_STAT + 640;
    float* b1s    = smf + OFF_STAT + 768;
    float* b2s    = smf + OFF_STAT + 832;

    const int tid = threadIdx.x;
    const int b   = blockIdx.x;
    const int g1 = 2 * b, g2 = 2 * b + 1;
    const int n1 = g_size[g1], n2 = g_size[g2];
    const int off1 = g_off[g1], off2 = g_off[g2];

    const int w    = tid >> 5, lane = tid & 31;
    const int g    = lane >> 2, t = lane & 3;

    // load W1 (stride 72) + biases + p1/p2 (zero padded, stride 68)
    for (int i = tid; i < 4096; i += NTHREADS) Ws[(i >> 6) * WSTR + (i & 63)] = W1g[i];
    if (tid < 64) { b1s[tid] = b1g[tid]; b2s[tid] = b2g[tid]; }
    for (int it = tid; it < MM * 16; it += NTHREADS) {
        int r = it >> 4, c4 = (it & 15) << 2;
        float4 z = make_float4(0.f, 0.f, 0.f, 0.f);
        float4 v1 = (r < n1) ? *(const float4*)(data + (size_t)(off1 + r) * DIM + c4) : z;
        float4 v2 = (r < n2) ? *(const float4*)(data + (size_t)(off2 + r) * DIM + c4) : z;
        *(float4*)(p1 + r * PSTR + c4) = v1;
        *(float4*)(p2 + r * PSTR + c4) = v2;
    }
    __syncthreads();

    // ---- h phase: h = relu(p @ W1 + b1), both halves concurrently ----
    {
        int half = w >> 3, mt = w & 7;
        int m0 = mt << 4;
        int n = half ? n2 : n1;
        const float* pin = half ? p2 : p1;
        float* hout = smf + (half ? OFF_H2 : OFF_H1);
        if (m0 < n) {
            float acc[8][4];
#pragma unroll
            for (int n8 = 0; n8 < 8; n8++) {
                float v0 = b1s[(n8 << 3) + 2 * t], v1 = b1s[(n8 << 3) + 2 * t + 1];
                acc[n8][0] = v0; acc[n8][1] = v1; acc[n8][2] = v0; acc[n8][3] = v1;
            }
            warp_gemm<false>(acc, pin, PSTR, 1, m0, Ws, WSTR, 1, 0, 8, g, t, nullptr);
#pragma unroll
            for (int n8 = 0; n8 < 8; n8++) {
                int c = (n8 << 3) + 2 * t;
                *(float2*)(hout + (m0 + g) * PSTR + c) =
                    make_float2(fmaxf(acc[n8][0], 0.f), fmaxf(acc[n8][1], 0.f));
                *(float2*)(hout + (m0 + g + 8) * PSTR + c) =
                    make_float2(fmaxf(acc[n8][2], 0.f), fmaxf(acc[n8][3], 0.f));
            }
        }
    }
    __syncthreads();
    // swap in W2
    for (int i = tid; i < 4096; i += NTHREADS) Ws[(i >> 6) * WSTR + (i & 63)] = W2g[i];
    __syncthreads();

    // ---- t phase: t = h @ W2 + b2, rows >= n zeroed (also zero-fill skipped tiles) ----
    {
        int half = w >> 3, mt = w & 7;
        int m0 = mt << 4;
        int n = half ? n2 : n1;
        const float* hin = smf + (half ? OFF_H2 : OFF_H1);
        float* tout = half ? t2 : t1;
        if (m0 < n) {
            float acc[8][4];
#pragma unroll
            for (int n8 = 0; n8 < 8; n8++) {
                float v0 = b2s[(n8 << 3) + 2 * t], v1 = b2s[(n8 << 3) + 2 * t + 1];
                acc[n8][0] = v0; acc[n8][1] = v1; acc[n8][2] = v0; acc[n8][3] = v1;
            }
            warp_gemm<false>(acc, hin, PSTR, 1, m0, Ws, WSTR, 1, 0, 8, g, t, nullptr);
            int r1 = m0 + g, r2 = m0 + g + 8;
            bool v1 = r1 < n, v2 = r2 < n;
#pragma unroll
            for (int n8 = 0; n8 < 8; n8++) {
                int c = (n8 << 3) + 2 * t;
                *(float2*)(tout + r1 * PSTR + c) =
                    v1 ? make_float2(acc[n8][0], acc[n8][1]) : make_float2(0.f, 0.f);
                *(float2*)(tout + r2 * PSTR + c) =
                    v2 ? make_float2(acc[n8][2], acc[n8][3]) : make_float2(0.f, 0.f);
            }
        } else {
            // zero the 16 rows so sim's B-reads see zeros
            for (int r = 0; r < 16; r++)
                for (int c = lane; c < 64; c += 32)
                    tout[(m0 + r) * PSTR + c] = 0.f;
        }
    }
    __syncthreads();

    // ---- sim = t1 @ t2^T : warp = (m-tile, n-half) ----
    {
        int mt = w >> 1, nh = w & 1;
        int m0 = mt << 4, nb = nh << 6;
        if (m0 < n1 && nb < n2) {
            float acc[8][4];
#pragma unroll
            for (int n8 = 0; n8 < 8; n8++) { acc[n8][0] = 0.f; acc[n8][1] = 0.f; acc[n8][2] = 0.f; acc[n8][3] = 0.f; }
            warp_gemm<false>(acc, t1, PSTR, 1, m0, t2, 1, PSTR, nb, 8, g, t, nullptr);
#pragma unroll
            for (int n8 = 0; n8 < 8; n8++) {
                int c = nb + (n8 << 3) + 2 * t;
                *(float2*)(simb + (m0 + g) * SSTR + c) = make_float2(acc[n8][0], acc[n8][1]);
                *(float2*)(simb + (m0 + g + 8) * SSTR + c) = make_float2(acc[n8][2], acc[n8][3]);
            }
        }
    }
    __syncthreads();

    // ---- stats (+ am/bn factors); EXACT bounds (padded sim entries are 0, not -inf) ----
    if (tid < 256) {
        int r = tid >> 1, h = tid & 1;
        const int nf = n2 >> 2;          // complete float4 blocks
        const int tl = n2 & 3;           // tail elements
        const bool own_tail = (tl != 0) && ((nf >> 4) == h);
        int c4s = h * 16, c4x = min(nf, c4s + 16);
        float mx = -CUDART_INF_F;
        if (r < n1) {
            const float* row = simb + r * SSTR;
            for (int c4 = c4s; c4 < c4x; c4++) {
                float4 v = *(const float4*)(row + c4 * 4);
                mx = fmaxf(mx, fmaxf(fmaxf(v.x, v.y), fmaxf(v.z, v.w)));
            }
            if (own_tail)
                for (int c = nf << 2; c < n2; c++) mx = fmaxf(mx, row[c]);
        }
        mx = fmaxf(mx, __shfl_xor_sync(0xffffffffu, mx, 1));
        float s = 0.f;
        if (r < n1) {
            const float* row = simb + r * SSTR;
            for (int c4 = c4s; c4 < c4x; c4++) {
                float4 v = *(const float4*)(row + c4 * 4);
                s += __expf(v.x - mx) + __expf(v.y - mx) + __expf(v.z - mx) + __expf(v.w - mx);
            }
            if (own_tail)
                for (int c = nf << 2; c < n2; c++) s += __expf(row[c] - mx);
        }
        s += __shfl_xor_sync(0xffffffffu, s, 1);
        if (h == 0) {
            if (r < n1) { rowmax[r] = mx; rowinv[r] = 1.f / s; am[r] = __expf(mx) * s; }
            else        { rowmax[r] = 0.f; rowinv[r] = 0.f; am[r] = 0.f; }
        }
    } else {
        int c = (tid - 256) >> 1, h = tid & 1;
        int rs = h * 64, re = min(n1, rs + 64);
        float mx = -CUDART_INF_F;
        if (c < n2) for (int r = rs; r < re; r++) mx = fmaxf(mx, simb[r * SSTR + c]);
        mx = fmaxf(mx, __shfl_xor_sync(0xffffffffu, mx, 1));
        float s = 0.f;
        if (c < n2) for (int r = rs; r < re; r++) s += __expf(simb[r * SSTR + c] - mx);
        s += __shfl_xor_sync(0xffffffffu, s, 1);
        if (h == 0) {
            if (c < n2) { colmax[c] = mx; colinv[c] = 1.f / s; bn[c] = __expf(-mx) / s; }
            else        { colmax[c] = 0.f; colinv[c] = 0.f; bn[c] = 0.f; }
        }
    }
    __syncthreads();

    // ---- materialize s1 (in-place) + stream s1/s2 to gmem ----
    {
        const float inv1 = 1.f / (float)(MM - n1);
        const float inv2 = 1.f / (float)(MM - n2);
        for (int it = tid; it < MM * 32; it += NTHREADS) {
            int m = it >> 5, n0 = (it & 31) << 2;
            float4 a, c;
            if (m < n1) {
                float4 v = *(const float4*)(simb + m * SSTR + n0);
                float rm = rowmax[m], ri = rowinv[m];
                float4 cm = *(const float4*)(colmax + n0);
                float4 ci = *(const float4*)(colinv + n0);
                a.x = (n0 + 0 < n2) ? __expf(v.x - rm) * ri : 0.f;
                a.y = (n0 + 1 < n2) ? __expf(v.y - rm) * ri : 0.f;
                a.z = (n0 + 2 < n2) ? __expf(v.z - rm) * ri : 0.f;
                a.w = (n0 + 3 < n2) ? __expf(v.w - rm) * ri : 0.f;
                c.x = (n0 + 0 < n2) ? __expf(v.x - cm.x) * ci.x : 0.f;
                c.y = (n0 + 1 < n2) ? __expf(v.y - cm.y) * ci.y : 0.f;
                c.z = (n0 + 2 < n2) ? __expf(v.z - cm.z) * ci.z : 0.f;
                c.w = (n0 + 3 < n2) ? __expf(v.w - cm.w) * ci.w : 0.f;
            } else {
                a.x = (n0 + 0 < n2) ? 0.f : inv2;
                a.y = (n0 + 1 < n2) ? 0.f : inv2;
                a.z = (n0 + 2 < n2) ? 0.f : inv2;
                a.w = (n0 + 3 < n2) ? 0.f : inv2;
                c.x = (n0 + 0 < n2) ? 0.f : inv1;
                c.y = (n0 + 1 < n2) ? 0.f : inv1;
                c.z = (n0 + 2 < n2) ? 0.f : inv1;
                c.w = (n0 + 3 < n2) ? 0.f : inv1;
            }
            size_t go = (size_t)b * (MM * MM) + (size_t)m * MM + n0;
            *(float4*)(s1_out + go) = a;
            *(float4*)(s2_out + go) = c;
            *(float4*)(simb + m * SSTR + n0) = a;
        }
    }
    __syncthreads();

    // ---- attention: qn = s1 @ p2 (warps 0-7), cn = (s1*am)^T @ p1 * bn (warps 8-15) ----
    if (w < 8) {
        int m0 = w << 4;
        if (m0 < n1) {
            float acc[8][4];
#pragma unroll
            for (int n8 = 0; n8 < 8; n8++) { acc[n8][0] = 0.f; acc[n8][1] = 0.f; acc[n8][2] = 0.f; acc[n8][3] = 0.f; }
            int ks = (n2 + 7) >> 3;
            warp_gemm<false>(acc, simb, SSTR, 1, m0, p2, PSTR, 1, 0, ks, g, t, nullptr);
            int m1 = m0 + g, m2 = m0 + g + 8;
#pragma unroll
            for (int n8 = 0; n8 < 8; n8++) {
                int c = (n8 << 3) + 2 * t;
                if (m1 < n1)
                    *(float2*)(res_out + (size_t)(off1 + m1) * DIM + c) = make_float2(acc[n8][0], acc[n8][1]);
                if (m2 < n1)
                    *(float2*)(res_out + (size_t)(off1 + m2) * DIM + c) = make_float2(acc[n8][2], acc[n8][3]);
            }
        }
    } else {
        int nn0 = (w - 8) << 4;
        if (nn0 < n2) {
            float acc[8][4];
#pragma unroll
            for (int n8 = 0; n8 < 8; n8++) { acc[n8][0] = 0.f; acc[n8][1] = 0.f; acc[n8][2] = 0.f; acc[n8][3] = 0.f; }
            int ks = (n1 + 7) >> 3;
            warp_gemm<true>(acc, simb, 1, SSTR, nn0, p1, PSTR, 1, 0, ks, g, t, am);
            int r1 = nn0 + g, r2 = nn0 + g + 8;
            float f1 = (r1 < MM) ? bn[r1] : 0.f;
            float f2 = (r2 < MM) ? bn[r2] : 0.f;
#pragma unroll
            for (int n8 = 0; n8 < 8; n8++) {
                int c = (n8 << 3) + 2 * t;
                if (r1 < n2)
                    *(float2*)(res_out + (size_t)(off2 + r1) * DIM + c) =
                        make_float2(acc[n8][0] * f1, acc[n8][1] * f1);
                if (r2 < n2)
                    *(float2*)(res_out + (size_t)(off2 + r2) * DIM + c) =
                        make_float2(acc[n8][2] * f2, acc[n8][3] * f2);
            }
        }
    }
}

extern "C" void kernel_launch(void* const* d_in, const int* in_sizes, int n_in,
                              void* d_out, int out_size) {
    const float* data = (const float*)d_in[0];
    const float* W1   = (const float*)d_in[1];
    const float* b1   = (const float*)d_in[2];
    const float* W2   = (const float*)d_in[3];
    const float* b2   = (const float*)d_in[4];
    const int*   sizes_raw = (const int*)d_in[5];

    float* out = (float*)d_out;
    size_t total_e = (size_t)in_sizes[0];        // total * DIM
    float* s1o = out + total_e;
    float* s2o = s1o + (size_t)NPAIRS * MM * MM;

    cudaFuncSetAttribute(cross_kernel, cudaFuncAttributeMaxDynamicSharedMemorySize, SMEM_BYTES);

    scan_kernel<<<1, 1024>>>(sizes_raw);
    cross_kernel<<<NPAIRS, NTHREADS, SMEM_BYTES>>>(data, W1, b1, W2, b2, out, s1o, s2o);
}

// round 8
// speedup vs baseline: 1.5019x; 1.5019x over previous
#include <cuda_runtime.h>
#include <math_constants.h>
#include <cstdint>

#define NGROUPS 4096
#define NPAIRS  2048
#define DIM     64
#define MM      128
#define PSTR    68     // fp32 stride for 64-wide tiles
#define WPS     36     // W plane stride (uint32 slots)
#define TPS     36     // t2 plane stride
#define S1PS    68     // s1row plane stride
#define SSTR    132    // sim fp32 stride
#define NTHREADS 512

// ---- smem float offsets ----
#define OFF_P1   0        // 8704
#define OFF_P2   8704     // 8704
#define OFF_WH   17408    // 2304 (64x36)
#define OFF_WL   19712    // 2304
#define OFF_H1   22016    // 8704
#define OFF_H2   30720    // 8704
#define OFF_SIM  22016    // overlay over h1/h2 (16896)
#define OFF_T1   39424    // 8704 fp32
#define OFF_T2H  48128    // 4608 (128x36)
#define OFF_T2L  52736    // 4608
#define OFF_S1H  39424    // overlay over t1 (8704)
#define OFF_S1L  48128    // overlay over t2 planes (8704)
#define OFF_STAT 57344    // rowmax,rowinv,colmax,colinv,am,bn (128 ea) = 768
#define SMEM_BYTES (58112 * 4)   // 232448 = max dynamic smem per CTA

__device__ int g_off[NGROUPS];
__device__ int g_size[NGROUPS];

__global__ void scan_kernel(const int* __restrict__ raw) {
    __shared__ int wsum[32];
    const int stride =
        (raw[1] == 0 && raw[3] == 0 && raw[5] == 0 && raw[7] == 0) ? 2 : 1;
    int tid = threadIdx.x;
    int base = tid * 4;
    int v[4]; int s = 0;
#pragma unroll
    for (int i = 0; i < 4; i++) { v[i] = s; s += raw[(base + i) * stride]; }
    int lane = tid & 31, w = tid >> 5;
    int x = s;
#pragma unroll
    for (int d = 1; d < 32; d <<= 1) { int y = __shfl_up_sync(0xffffffffu, x, d); if (lane >= d) x += y; }
    if (lane == 31) wsum[w] = x;
    int excl = x - s;
    __syncthreads();
    if (w == 0) {
        int ws = wsum[lane]; int xx = ws;
#pragma unroll
        for (int d = 1; d < 32; d <<= 1) { int y = __shfl_up_sync(0xffffffffu, xx, d); if (lane >= d) xx += y; }
        wsum[lane] = xx - ws;
    }
    __syncthreads();
    int off = wsum[w] + excl;
#pragma unroll
    for (int i = 0; i < 4; i++) {
        g_off[base + i]  = off + v[i];
        g_size[base + i] = raw[(base + i) * stride];
    }
}

// ---- bf16 split helpers ----
// pack (x0,x1) -> hi reg (low16 = bf16(x0)), lo reg = residuals
__device__ __forceinline__ void split_pair(float x0, float x1, uint32_t& h, uint32_t& l) {
    asm("cvt.rn.bf16x2.f32 %0, %1, %2;" : "=r"(h) : "f"(x1), "f"(x0));
    float h0 = __uint_as_float(h << 16);
    float h1 = __uint_as_float(h & 0xFFFF0000u);
    float l0 = x0 - h0, l1 = x1 - h1;
    asm("cvt.rn.bf16x2.f32 %0, %1, %2;" : "=r"(l) : "f"(l1), "f"(l0));
}

__device__ __forceinline__ void mma16(float* c, const uint32_t* a, const uint32_t* b) {
    asm volatile("mma.sync.aligned.m16n8k16.row.col.f32.bf16.bf16.f32 "
        "{%0,%1,%2,%3},{%4,%5,%6,%7},{%8,%9},{%0,%1,%2,%3};"
        : "+f"(c[0]), "+f"(c[1]), "+f"(c[2]), "+f"(c[3])
        : "r"(a[0]), "r"(a[1]), "r"(a[2]), "r"(a[3]), "r"(b[0]), "r"(b[1]));
}

// A fragment from fp32 row-major (stride AS), split in-flight.
__device__ __forceinline__ void load_a_rm(const float* __restrict__ A, int AS, int r0, int k0,
                                          int g, int t, uint32_t* ah, uint32_t* al) {
    const float* a0p = A + (r0 + g) * AS + k0 + 2 * t;
    const float* a1p = a0p + 8 * AS;
    float2 x0 = *(const float2*)a0p;
    float2 x1 = *(const float2*)a1p;
    float2 x2 = *(const float2*)(a0p + 8);
    float2 x3 = *(const float2*)(a1p + 8);
    split_pair(x0.x, x0.y, ah[0], al[0]);
    split_pair(x1.x, x1.y, ah[1], al[1]);
    split_pair(x2.x, x2.y, ah[2], al[2]);
    split_pair(x3.x, x3.y, ah[3], al[3]);
}

// 16x64 warp GEMM: A fp32 row-major (in-flight split), B packed hi/lo planes [n][k/2].
__device__ __forceinline__ void gemm_packedB(
    float acc[8][4], const float* __restrict__ Afp, int AS, int r0,
    const uint32_t* __restrict__ Bh, const uint32_t* __restrict__ Bl, int BPS,
    int nbase, int ks16, int g, int t)
{
    for (int kk = 0; kk < ks16; kk++) {
        int k0 = kk << 4;
        uint32_t ah[4], al[4];
        load_a_rm(Afp, AS, r0, k0, g, t, ah, al);
        int slot = (k0 >> 1) + t;
#pragma unroll
        for (int n8 = 0; n8 < 8; n8++) {
            int nr = nbase + (n8 << 3) + g;
            uint32_t bh[2] = { Bh[nr * BPS + slot], Bh[nr * BPS + slot + 4] };
            uint32_t bl[2] = { Bl[nr * BPS + slot], Bl[nr * BPS + slot + 4] };
            mma16(acc[n8], ah, bh);
            mma16(acc[n8], al, bh);
            mma16(acc[n8], ah, bl);
        }
    }
}

__global__ __launch_bounds__(NTHREADS) void cross_kernel(
    const float* __restrict__ data, const float* __restrict__ W1g,
    const float* __restrict__ b1g, const float* __restrict__ W2g,
    const float* __restrict__ b2g,
    float* __restrict__ res_out, float* __restrict__ s1_out, float* __restrict__ s2_out)
{
    extern __shared__ float smf[];
    float* p1 = smf + OFF_P1;
    float* p2 = smf + OFF_P2;
    uint32_t* Wh = (uint32_t*)(smf + OFF_WH);
    uint32_t* Wl = (uint32_t*)(smf + OFF_WL);
    float* simb = smf + OFF_SIM;
    float* t1   = smf + OFF_T1;
    uint32_t* T2h = (uint32_t*)(smf + OFF_T2H);
    uint32_t* T2l = (uint32_t*)(smf + OFF_T2L);
    uint32_t* S1h = (uint32_t*)(smf + OFF_S1H);
    uint32_t* S1l = (uint32_t*)(smf + OFF_S1L);
    float* rowmax = smf + OFF_STAT;
    float* rowinv = smf + OFF_STAT + 128;
    float* colmax = smf + OFF_STAT + 256;
    float* colinv = smf + OFF_STAT + 384;
    float* am     = smf + OFF_STAT + 512;
    float* bn     = smf + OFF_STAT + 640;

    const int tid = threadIdx.x;
    const int b   = blockIdx.x;
    const int g1 = 2 * b, g2 = 2 * b + 1;
    const int n1 = g_size[g1], n2 = g_size[g2];
    const int off1 = g_off[g1], off2 = g_off[g2];

    const int w = tid >> 5, lane = tid & 31;
    const int g = lane >> 2, t = lane & 3;

    // ---- load: pack W1 planes; p1/p2 fp32 zero-padded ----
    for (int i = tid; i < 2048; i += NTHREADS) {
        int n = i & 63, ks = i >> 6;
        uint32_t h, l;
        split_pair(W1g[(2 * ks) * 64 + n], W1g[(2 * ks + 1) * 64 + n], h, l);
        Wh[n * WPS + ks] = h; Wl[n * WPS + ks] = l;
    }
    for (int it = tid; it < MM * 16; it += NTHREADS) {
        int r = it >> 4, c4 = (it & 15) << 2;
        float4 z = make_float4(0.f, 0.f, 0.f, 0.f);
        float4 v1 = (r < n1) ? *(const float4*)(data + (size_t)(off1 + r) * DIM + c4) : z;
        float4 v2 = (r < n2) ? *(const float4*)(data + (size_t)(off2 + r) * DIM + c4) : z;
        *(float4*)(p1 + r * PSTR + c4) = v1;
        *(float4*)(p2 + r * PSTR + c4) = v2;
    }
    __syncthreads();

    // ---- H: h = relu(p @ W1 + b1), warps = (half, m-tile) ----
    {
        int half = w >> 3, mt = w & 7;
        int m0 = mt << 4;
        int n = half ? n2 : n1;
        const float* pin = half ? p2 : p1;
        float* hout = smf + (half ? OFF_H2 : OFF_H1);
        if (m0 < n) {
            float acc[8][4];
#pragma unroll
            for (int n8 = 0; n8 < 8; n8++) {
                float2 bv = __ldg((const float2*)(b1g + (n8 << 3) + 2 * t));
                acc[n8][0] = bv.x; acc[n8][1] = bv.y; acc[n8][2] = bv.x; acc[n8][3] = bv.y;
            }
            gemm_packedB(acc, pin, PSTR, m0, Wh, Wl, WPS, 0, 4, g, t);
#pragma unroll
            for (int n8 = 0; n8 < 8; n8++) {
                int c = (n8 << 3) + 2 * t;
                *(float2*)(hout + (m0 + g) * PSTR + c) =
                    make_float2(fmaxf(acc[n8][0], 0.f), fmaxf(acc[n8][1], 0.f));
                *(float2*)(hout + (m0 + g + 8) * PSTR + c) =
                    make_float2(fmaxf(acc[n8][2], 0.f), fmaxf(acc[n8][3], 0.f));
            }
        }
    }
    __syncthreads();
    // swap: pack W2 planes over W1
    for (int i = tid; i < 2048; i += NTHREADS) {
        int n = i & 63, ks = i >> 6;
        uint32_t h, l;
        split_pair(W2g[(2 * ks) * 64 + n], W2g[(2 * ks + 1) * 64 + n], h, l);
        Wh[n * WPS + ks] = h; Wl[n * WPS + ks] = l;
    }
    __syncthreads();

    // ---- T: t = h @ W2 + b2; half0 -> t1 fp32, half1 -> t2 packed planes ----
    {
        int half = w >> 3, mt = w & 7;
        int m0 = mt << 4;
        int n = half ? n2 : n1;
        const float* hin = smf + (half ? OFF_H2 : OFF_H1);
        if (m0 < n) {
            float acc[8][4];
#pragma unroll
            for (int n8 = 0; n8 < 8; n8++) {
                float2 bv = __ldg((const float2*)(b2g + (n8 << 3) + 2 * t));
                acc[n8][0] = bv.x; acc[n8][1] = bv.y; acc[n8][2] = bv.x; acc[n8][3] = bv.y;
            }
            gemm_packedB(acc, hin, PSTR, m0, Wh, Wl, WPS, 0, 4, g, t);
            if (half == 0) {
#pragma unroll
                for (int n8 = 0; n8 < 8; n8++) {
                    int c = (n8 << 3) + 2 * t;
                    *(float2*)(t1 + (m0 + g) * PSTR + c) = make_float2(acc[n8][0], acc[n8][1]);
                    *(float2*)(t1 + (m0 + g + 8) * PSTR + c) = make_float2(acc[n8][2], acc[n8][3]);
                }
            } else {
#pragma unroll
                for (int n8 = 0; n8 < 8; n8++) {
                    int cs = (n8 << 2) + t;
                    uint32_t h, l;
                    split_pair(acc[n8][0], acc[n8][1], h, l);
                    T2h[(m0 + g) * TPS + cs] = h; T2l[(m0 + g) * TPS + cs] = l;
                    split_pair(acc[n8][2], acc[n8][3], h, l);
                    T2h[(m0 + g + 8) * TPS + cs] = h; T2l[(m0 + g + 8) * TPS + cs] = l;
                }
            }
        }
    }
    __syncthreads();

    // ---- sim = t1 @ t2^T : warps = (m-tile, n-half); A fp32 t1, B packed t2 ----
    {
        int mt = w >> 1, nh = w & 1;
        int m0 = mt << 4, nb = nh << 6;
        if (m0 < n1 && nb < n2) {
            float acc[8][4];
#pragma unroll
            for (int n8 = 0; n8 < 8; n8++) { acc[n8][0] = 0.f; acc[n8][1] = 0.f; acc[n8][2] = 0.f; acc[n8][3] = 0.f; }
            gemm_packedB(acc, t1, PSTR, m0, T2h, T2l, TPS, nb, 4, g, t);
#pragma unroll
            for (int n8 = 0; n8 < 8; n8++) {
                int c = nb + (n8 << 3) + 2 * t;
                *(float2*)(simb + (m0 + g) * SSTR + c) = make_float2(acc[n8][0], acc[n8][1]);
                *(float2*)(simb + (m0 + g + 8) * SSTR + c) = make_float2(acc[n8][2], acc[n8][3]);
            }
        }
    }
    __syncthreads();

    // ---- stats (exact bounds) + am/bn ----
    if (tid < 256) {
        int r = tid >> 1, h = tid & 1;
        const int nf = n2 >> 2;
        const int tl = n2 & 3;
        const bool own_tail = (tl != 0) && ((nf >> 4) == h);
        int c4s = h * 16, c4x = min(nf, c4s + 16);
        float mx = -CUDART_INF_F;
        if (r < n1) {
            const float* row = simb + r * SSTR;
            for (int c4 = c4s; c4 < c4x; c4++) {
                float4 v = *(const float4*)(row + c4 * 4);
                mx = fmaxf(mx, fmaxf(fmaxf(v.x, v.y), fmaxf(v.z, v.w)));
            }
            if (own_tail)
                for (int c = nf << 2; c < n2; c++) mx = fmaxf(mx, row[c]);
        }
        mx = fmaxf(mx, __shfl_xor_sync(0xffffffffu, mx, 1));
        float s = 0.f;
        if (r < n1) {
            const float* row = simb + r * SSTR;
            for (int c4 = c4s; c4 < c4x; c4++) {
                float4 v = *(const float4*)(row + c4 * 4);
                s += __expf(v.x - mx) + __expf(v.y - mx) + __expf(v.z - mx) + __expf(v.w - mx);
            }
            if (own_tail)
                for (int c = nf << 2; c < n2; c++) s += __expf(row[c] - mx);
        }
        s += __shfl_xor_sync(0xffffffffu, s, 1);
        if (h == 0) {
            if (r < n1) { rowmax[r] = mx; rowinv[r] = 1.f / s; am[r] = __expf(mx) * s; }
            else        { rowmax[r] = 0.f; rowinv[r] = 0.f; am[r] = 0.f; }
        }
    } else {
        int c = (tid - 256) >> 1, h = tid & 1;
        int rs = h * 64, re = min(n1, rs + 64);
        float mx = -CUDART_INF_F;
        if (c < n2) for (int r = rs; r < re; r++) mx = fmaxf(mx, simb[r * SSTR + c]);
        mx = fmaxf(mx, __shfl_xor_sync(0xffffffffu, mx, 1));
        float s = 0.f;
        if (c < n2) for (int r = rs; r < re; r++) s += __expf(simb[r * SSTR + c] - mx);
        s += __shfl_xor_sync(0xffffffffu, s, 1);
        if (h == 0) {
            if (c < n2) { colmax[c] = mx; colinv[c] = 1.f / s; bn[c] = __expf(-mx) / s; }
            else        { colmax[c] = 0.f; colinv[c] = 0.f; bn[c] = 0.f; }
        }
    }
    __syncthreads();

    // ---- materialize: s1/s2 -> gmem; s1 fp32 -> simb; s1 packed planes -> t-region ----
    {
        const float inv1 = 1.f / (float)(MM - n1);
        const float inv2 = 1.f / (float)(MM - n2);
        for (int it = tid; it < MM * 32; it += NTHREADS) {
            int m = it >> 5, n0 = (it & 31) << 2;
            float4 a, c;
            if (m < n1) {
                float4 v = *(const float4*)(simb + m * SSTR + n0);
                float rm = rowmax[m], ri = rowinv[m];
                float4 cm = *(const float4*)(colmax + n0);
                float4 ci = *(const float4*)(colinv + n0);
                a.x = (n0 + 0 < n2) ? __expf(v.x - rm) * ri : 0.f;
                a.y = (n0 + 1 < n2) ? __expf(v.y - rm) * ri : 0.f;
                a.z = (n0 + 2 < n2) ? __expf(v.z - rm) * ri : 0.f;
                a.w = (n0 + 3 < n2) ? __expf(v.w - rm) * ri : 0.f;
                c.x = (n0 + 0 < n2) ? __expf(v.x - cm.x) * ci.x : 0.f;
                c.y = (n0 + 1 < n2) ? __expf(v.y - cm.y) * ci.y : 0.f;
                c.z = (n0 + 2 < n2) ? __expf(v.z - cm.z) * ci.z : 0.f;
                c.w = (n0 + 3 < n2) ? __expf(v.w - cm.w) * ci.w : 0.f;
            } else {
                a.x = (n0 + 0 < n2) ? 0.f : inv2;
                a.y = (n0 + 1 < n2) ? 0.f : inv2;
                a.z = (n0 + 2 < n2) ? 0.f : inv2;
                a.w = (n0 + 3 < n2) ? 0.f : inv2;
                c.x = (n0 + 0 < n2) ? 0.f : inv1;
                c.y = (n0 + 1 < n2) ? 0.f : inv1;
                c.z = (n0 + 2 < n2) ? 0.f : inv1;
                c.w = (n0 + 3 < n2) ? 0.f : inv1;
            }
            size_t go = (size_t)b * (MM * MM) + (size_t)m * MM + n0;
            *(float4*)(s1_out + go) = a;
            *(float4*)(s2_out + go) = c;
            *(float4*)(simb + m * SSTR + n0) = a;
            uint32_t h0, l0, h1, l1;
            split_pair(a.x, a.y, h0, l0);
            split_pair(a.z, a.w, h1, l1);
            *(uint2*)(S1h + m * S1PS + (n0 >> 1)) = make_uint2(h0, h1);
            *(uint2*)(S1l + m * S1PS + (n0 >> 1)) = make_uint2(l0, l1);
        }
    }
    __syncthreads();

    // ---- attention ----
    if (w < 8) {
        // qn = s1 @ p2 : A = packed s1row, B = fp32 p2 (in-flight split)
        int m0 = w << 4;
        if (m0 < n1) {
            float acc[8][4];
#pragma unroll
            for (int n8 = 0; n8 < 8; n8++) { acc[n8][0] = 0.f; acc[n8][1] = 0.f; acc[n8][2] = 0.f; acc[n8][3] = 0.f; }
            int ks16 = (n2 + 15) >> 4;
            for (int kk = 0; kk < ks16; kk++) {
                int k0 = kk << 4;
                int as = (m0 + g) * S1PS + (k0 >> 1) + t;
                int as8 = as + 8 * S1PS;
                uint32_t ah[4] = { S1h[as], S1h[as8], S1h[as + 4], S1h[as8 + 4] };
                uint32_t al[4] = { S1l[as], S1l[as8], S1l[as + 4], S1l[as8 + 4] };
#pragma unroll
                for (int n8 = 0; n8 < 8; n8++) {
                    int nc = (n8 << 3) + g;
                    const float* bp = p2 + (k0 + 2 * t) * PSTR + nc;
                    uint32_t bh[2], bl[2];
                    split_pair(bp[0], bp[PSTR], bh[0], bl[0]);
                    split_pair(bp[8 * PSTR], bp[9 * PSTR], bh[1], bl[1]);
                    mma16(acc[n8], ah, bh);
                    mma16(acc[n8], al, bh);
                    mma16(acc[n8], ah, bl);
                }
            }
            int m1 = m0 + g, m2 = m0 + g + 8;
#pragma unroll
            for (int n8 = 0; n8 < 8; n8++) {
                int c = (n8 << 3) + 2 * t;
                if (m1 < n1)
                    *(float2*)(res_out + (size_t)(off1 + m1) * DIM + c) = make_float2(acc[n8][0], acc[n8][1]);
                if (m2 < n1)
                    *(float2*)(res_out + (size_t)(off1 + m2) * DIM + c) = make_float2(acc[n8][2], acc[n8][3]);
            }
        }
    } else {
        // cn = (s1*am)^T @ p1, scaled by bn : A = fp32 simb cols (in-flight), B = fp32 p1
        int nn0 = (w - 8) << 4;
        if (nn0 < n2) {
            float acc[8][4];
#pragma unroll
            for (int n8 = 0; n8 < 8; n8++) { acc[n8][0] = 0.f; acc[n8][1] = 0.f; acc[n8][2] = 0.f; acc[n8][3] = 0.f; }
            int ks16 = (n1 + 15) >> 4;
            for (int kk = 0; kk < ks16; kk++) {
                int k0 = kk << 4;
                int kr = k0 + 2 * t;
                float am0 = am[kr], am1 = am[kr + 1], am2 = am[kr + 8], am3 = am[kr + 9];
                const float* s0 = simb + kr * SSTR + nn0 + g;
                const float* s8 = s0 + 8 * SSTR;
                uint32_t ah[4], al[4];
                split_pair(s0[0] * am0, s0[SSTR] * am1, ah[0], al[0]);
                split_pair(s0[8] * am0, s0[SSTR + 8] * am1, ah[1], al[1]);
                split_pair(s8[0] * am2, s8[SSTR] * am3, ah[2], al[2]);
                split_pair(s8[8] * am2, s8[SSTR + 8] * am3, ah[3], al[3]);
#pragma unroll
                for (int n8 = 0; n8 < 8; n8++) {
                    int nc = (n8 << 3) + g;
                    const float* bp = p1 + (k0 + 2 * t) * PSTR + nc;
                    uint32_t bh[2], bl[2];
                    split_pair(bp[0], bp[PSTR], bh[0], bl[0]);
                    split_pair(bp[8 * PSTR], bp[9 * PSTR], bh[1], bl[1]);
                    mma16(acc[n8], ah, bh);
                    mma16(acc[n8], al, bh);
                    mma16(acc[n8], ah, bl);
                }
            }
            int r1 = nn0 + g, r2 = nn0 + g + 8;
            float f1 = bn[r1], f2 = bn[r2];
#pragma unroll
            for (int n8 = 0; n8 < 8; n8++) {
                int c = (n8 << 3) + 2 * t;
                if (r1 < n2)
                    *(float2*)(res_out + (size_t)(off2 + r1) * DIM + c) =
                        make_float2(acc[n8][0] * f1, acc[n8][1] * f1);
                if (r2 < n2)
                    *(float2*)(res_out + (size_t)(off2 + r2) * DIM + c) =
                        make_float2(acc[n8][2] * f2, acc[n8][3] * f2);
            }
        }
    }
}

extern "C" void kernel_launch(void* const* d_in, const int* in_sizes, int n_in,
                              void* d_out, int out_size) {
    const float* data = (const float*)d_in[0];
    const float* W1   = (const float*)d_in[1];
    const float* b1   = (const float*)d_in[2];
    const float* W2   = (const float*)d_in[3];
    const float* b2   = (const float*)d_in[4];
    const int*   sizes_raw = (const int*)d_in[5];

    float* out = (float*)d_out;
    size_t total_e = (size_t)in_sizes[0];        // total * DIM
    float* s1o = out + total_e;
    float* s2o = s1o + (size_t)NPAIRS * MM * MM;

    cudaFuncSetAttribute(cross_kernel, cudaFuncAttributeMaxDynamicSharedMemorySize, SMEM_BYTES);

    scan_kernel<<<1, 1024>>>(sizes_raw);
    cross_kernel<<<NPAIRS, NTHREADS, SMEM_BYTES>>>(data, W1, b1, W2, b2, out, s1o, s2o);
}

// round 9
// speedup vs baseline: 1.6406x; 1.0923x over previous
#include <cuda_runtime.h>
#include <math_constants.h>
#include <cstdint>

#define NGROUPS 4096
#define NPAIRS  2048
#define DIM     64
#define MM      128
#define PSTR    68     // fp32 stride for 64-wide tiles
#define WPS     36     // W plane stride (uint32 slots)
#define TPS     36     // t2 plane stride
#define S1PS    68     // s1row plane stride
#define SSTR    132    // sim fp32 stride
#define NTHREADS 1024

// ---- smem float offsets ----
#define OFF_P1   0        // 8704
#define OFF_P2   8704     // 8704
#define OFF_WH   17408    // 2304 (64x36)
#define OFF_WL   19712    // 2304
#define OFF_H1   22016    // 8704
#define OFF_H2   30720    // 8704
#define OFF_SIM  22016    // overlay over h1/h2 (16896)
#define OFF_T1   39424    // 8704 fp32
#define OFF_T2H  48128    // 4608 (128x36)
#define OFF_T2L  52736    // 4608
#define OFF_S1H  39424    // overlay over t1 (8704)
#define OFF_S1L  48128    // overlay over t2 planes (8704)
#define OFF_STAT 57344    // rowmax,rowinv,colmax,colinv,am,bn (128 ea) = 768
#define SMEM_BYTES (58112 * 4)   // 232448

__device__ int g_off[NGROUPS];
__device__ int g_size[NGROUPS];

__global__ void scan_kernel(const int* __restrict__ raw) {
    __shared__ int wsum[32];
    const int stride =
        (raw[1] == 0 && raw[3] == 0 && raw[5] == 0 && raw[7] == 0) ? 2 : 1;
    int tid = threadIdx.x;
    int base = tid * 4;
    int v[4]; int s = 0;
#pragma unroll
    for (int i = 0; i < 4; i++) { v[i] = s; s += raw[(base + i) * stride]; }
    int lane = tid & 31, w = tid >> 5;
    int x = s;
#pragma unroll
    for (int d = 1; d < 32; d <<= 1) { int y = __shfl_up_sync(0xffffffffu, x, d); if (lane >= d) x += y; }
    if (lane == 31) wsum[w] = x;
    int excl = x - s;
    __syncthreads();
    if (w == 0) {
        int ws = wsum[lane]; int xx = ws;
#pragma unroll
        for (int d = 1; d < 32; d <<= 1) { int y = __shfl_up_sync(0xffffffffu, xx, d); if (lane >= d) xx += y; }
        wsum[lane] = xx - ws;
    }
    __syncthreads();
    int off = wsum[w] + excl;
#pragma unroll
    for (int i = 0; i < 4; i++) {
        g_off[base + i]  = off + v[i];
        g_size[base + i] = raw[(base + i) * stride];
    }
}

// ---- bf16 split helpers ----
__device__ __forceinline__ void split_pair(float x0, float x1, uint32_t& h, uint32_t& l) {
    asm("cvt.rn.bf16x2.f32 %0, %1, %2;" : "=r"(h) : "f"(x1), "f"(x0));
    float h0 = __uint_as_float(h << 16);
    float h1 = __uint_as_float(h & 0xFFFF0000u);
    float l0 = x0 - h0, l1 = x1 - h1;
    asm("cvt.rn.bf16x2.f32 %0, %1, %2;" : "=r"(l) : "f"(l1), "f"(l0));
}

__device__ __forceinline__ void mma16(float* c, const uint32_t* a, const uint32_t* b) {
    asm volatile("mma.sync.aligned.m16n8k16.row.col.f32.bf16.bf16.f32 "
        "{%0,%1,%2,%3},{%4,%5,%6,%7},{%8,%9},{%0,%1,%2,%3};"
        : "+f"(c[0]), "+f"(c[1]), "+f"(c[2]), "+f"(c[3])
        : "r"(a[0]), "r"(a[1]), "r"(a[2]), "r"(a[3]), "r"(b[0]), "r"(b[1]));
}

__device__ __forceinline__ void load_a_rm(const float* __restrict__ A, int AS, int r0, int k0,
                                          int g, int t, uint32_t* ah, uint32_t* al) {
    const float* a0p = A + (r0 + g) * AS + k0 + 2 * t;
    const float* a1p = a0p + 8 * AS;
    float2 x0 = *(const float2*)a0p;
    float2 x1 = *(const float2*)a1p;
    float2 x2 = *(const float2*)(a0p + 8);
    float2 x3 = *(const float2*)(a1p + 8);
    split_pair(x0.x, x0.y, ah[0], al[0]);
    split_pair(x1.x, x1.y, ah[1], al[1]);
    split_pair(x2.x, x2.y, ah[2], al[2]);
    split_pair(x3.x, x3.y, ah[3], al[3]);
}

// 16x32 warp GEMM: A fp32 row-major (in-flight split), B packed planes. 4 n-frags.
__device__ __forceinline__ void gemm_packedB32(
    float acc[4][4], const float* __restrict__ Afp, int AS, int r0,
    const uint32_t* __restrict__ Bh, const uint32_t* __restrict__ Bl, int BPS,
    int nbase, int ks16, int g, int t)
{
    for (int kk = 0; kk < ks16; kk++) {
        int k0 = kk << 4;
        uint32_t ah[4], al[4];
        load_a_rm(Afp, AS, r0, k0, g, t, ah, al);
        int slot = (k0 >> 1) + t;
#pragma unroll
        for (int n8 = 0; n8 < 4; n8++) {
            int nr = nbase + (n8 << 3) + g;
            uint32_t bh[2] = { Bh[nr * BPS + slot], Bh[nr * BPS + slot + 4] };
            uint32_t bl[2] = { Bl[nr * BPS + slot], Bl[nr * BPS + slot + 4] };
            mma16(acc[n8], ah, bh);
            mma16(acc[n8], al, bh);
            mma16(acc[n8], ah, bl);
        }
    }
}

__global__ __launch_bounds__(NTHREADS) void cross_kernel(
    const float* __restrict__ data, const float* __restrict__ W1g,
    const float* __restrict__ b1g, const float* __restrict__ W2g,
    const float* __restrict__ b2g,
    float* __restrict__ res_out, float* __restrict__ s1_out, float* __restrict__ s2_out)
{
    extern __shared__ float smf[];
    float* p1 = smf + OFF_P1;
    float* p2 = smf + OFF_P2;
    uint32_t* Wh = (uint32_t*)(smf + OFF_WH);
    uint32_t* Wl = (uint32_t*)(smf + OFF_WL);
    float* simb = smf + OFF_SIM;
    float* t1   = smf + OFF_T1;
    uint32_t* T2h = (uint32_t*)(smf + OFF_T2H);
    uint32_t* T2l = (uint32_t*)(smf + OFF_T2L);
    uint32_t* S1h = (uint32_t*)(smf + OFF_S1H);
    uint32_t* S1l = (uint32_t*)(smf + OFF_S1L);
    float* rowmax = smf + OFF_STAT;
    float* rowinv = smf + OFF_STAT + 128;
    float* colmax = smf + OFF_STAT + 256;
    float* colinv = smf + OFF_STAT + 384;
    float* am     = smf + OFF_STAT + 512;
    float* bn     = smf + OFF_STAT + 640;

    const int tid = threadIdx.x;
    const int b   = blockIdx.x;
    const int gp1 = 2 * b, gp2 = 2 * b + 1;
    const int n1 = g_size[gp1], n2 = g_size[gp2];
    const int off1 = g_off[gp1], off2 = g_off[gp2];

    const int w = tid >> 5, lane = tid & 31;
    const int g = lane >> 2, t = lane & 3;

    // ---- load: pack W1 planes; p1/p2 fp32 zero-padded ----
    for (int i = tid; i < 2048; i += NTHREADS) {
        int n = i & 63, ks = i >> 6;
        uint32_t h, l;
        split_pair(W1g[(2 * ks) * 64 + n], W1g[(2 * ks + 1) * 64 + n], h, l);
        Wh[n * WPS + ks] = h; Wl[n * WPS + ks] = l;
    }
    for (int it = tid; it < MM * 16; it += NTHREADS) {
        int r = it >> 4, c4 = (it & 15) << 2;
        float4 z = make_float4(0.f, 0.f, 0.f, 0.f);
        float4 v1 = (r < n1) ? *(const float4*)(data + (size_t)(off1 + r) * DIM + c4) : z;
        float4 v2 = (r < n2) ? *(const float4*)(data + (size_t)(off2 + r) * DIM + c4) : z;
        *(float4*)(p1 + r * PSTR + c4) = v1;
        *(float4*)(p2 + r * PSTR + c4) = v2;
    }
    __syncthreads();

    // ---- H: h = relu(p @ W1 + b1); 32 jobs = (half, m-tile, n-half32) ----
    {
        int half = w >> 4, mt = (w >> 1) & 7, nh = w & 1;
        int m0 = mt << 4, nb = nh << 5;
        int n = half ? n2 : n1;
        const float* pin = half ? p2 : p1;
        float* hout = smf + (half ? OFF_H2 : OFF_H1);
        if (m0 < n) {
            float acc[4][4];
#pragma unroll
            for (int n8 = 0; n8 < 4; n8++) {
                float2 bv = __ldg((const float2*)(b1g + nb + (n8 << 3) + 2 * t));
                acc[n8][0] = bv.x; acc[n8][1] = bv.y; acc[n8][2] = bv.x; acc[n8][3] = bv.y;
            }
            gemm_packedB32(acc, pin, PSTR, m0, Wh, Wl, WPS, nb, 4, g, t);
#pragma unroll
            for (int n8 = 0; n8 < 4; n8++) {
                int c = nb + (n8 << 3) + 2 * t;
                *(float2*)(hout + (m0 + g) * PSTR + c) =
                    make_float2(fmaxf(acc[n8][0], 0.f), fmaxf(acc[n8][1], 0.f));
                *(float2*)(hout + (m0 + g + 8) * PSTR + c) =
                    make_float2(fmaxf(acc[n8][2], 0.f), fmaxf(acc[n8][3], 0.f));
            }
        }
    }
    __syncthreads();
    // swap: pack W2 planes
    for (int i = tid; i < 2048; i += NTHREADS) {
        int n = i & 63, ks = i >> 6;
        uint32_t h, l;
        split_pair(W2g[(2 * ks) * 64 + n], W2g[(2 * ks + 1) * 64 + n], h, l);
        Wh[n * WPS + ks] = h; Wl[n * WPS + ks] = l;
    }
    __syncthreads();

    // ---- T: t = h @ W2 + b2; half0 -> t1 fp32, half1 -> t2 packed planes ----
    {
        int half = w >> 4, mt = (w >> 1) & 7, nh = w & 1;
        int m0 = mt << 4, nb = nh << 5;
        int n = half ? n2 : n1;
        const float* hin = smf + (half ? OFF_H2 : OFF_H1);
        if (m0 < n) {
            float acc[4][4];
#pragma unroll
            for (int n8 = 0; n8 < 4; n8++) {
                float2 bv = __ldg((const float2*)(b2g + nb + (n8 << 3) + 2 * t));
                acc[n8][0] = bv.x; acc[n8][1] = bv.y; acc[n8][2] = bv.x; acc[n8][3] = bv.y;
            }
            gemm_packedB32(acc, hin, PSTR, m0, Wh, Wl, WPS, nb, 4, g, t);
            if (half == 0) {
#pragma unroll
                for (int n8 = 0; n8 < 4; n8++) {
                    int c = nb + (n8 << 3) + 2 * t;
                    *(float2*)(t1 + (m0 + g) * PSTR + c) = make_float2(acc[n8][0], acc[n8][1]);
                    *(float2*)(t1 + (m0 + g + 8) * PSTR + c) = make_float2(acc[n8][2], acc[n8][3]);
                }
            } else {
#pragma unroll
                for (int n8 = 0; n8 < 4; n8++) {
                    int cs = (nb >> 1) + (n8 << 2) + t;
                    uint32_t h, l;
                    split_pair(acc[n8][0], acc[n8][1], h, l);
                    T2h[(m0 + g) * TPS + cs] = h; T2l[(m0 + g) * TPS + cs] = l;
                    split_pair(acc[n8][2], acc[n8][3], h, l);
                    T2h[(m0 + g + 8) * TPS + cs] = h; T2l[(m0 + g + 8) * TPS + cs] = l;
                }
            }
        }
    }
    __syncthreads();

    // ---- sim = t1 @ t2^T ; 32 jobs = (m-tile, n-quarter32) ----
    {
        int mt = w >> 2, nq = w & 3;
        int m0 = mt << 4, nb = nq << 5;
        if (m0 < n1 && nb < n2) {
            float acc[4][4];
#pragma unroll
            for (int n8 = 0; n8 < 4; n8++) { acc[n8][0] = 0.f; acc[n8][1] = 0.f; acc[n8][2] = 0.f; acc[n8][3] = 0.f; }
            gemm_packedB32(acc, t1, PSTR, m0, T2h, T2l, TPS, nb, 4, g, t);
#pragma unroll
            for (int n8 = 0; n8 < 4; n8++) {
                int c = nb + (n8 << 3) + 2 * t;
                *(float2*)(simb + (m0 + g) * SSTR + c) = make_float2(acc[n8][0], acc[n8][1]);
                *(float2*)(simb + (m0 + g + 8) * SSTR + c) = make_float2(acc[n8][2], acc[n8][3]);
            }
        }
    }
    __syncthreads();

    // ---- stats (exact bounds): 4 threads/row (tid<512), 4 threads/col (512..1023) ----
    if (tid < 512) {
        int r = tid >> 2, h = tid & 3;
        const int nf = n2 >> 2;
        const int tl = n2 & 3;
        const bool own_tail = (tl != 0) && ((nf >> 3) == h);
        int c4s = h * 8, c4x = min(nf, c4s + 8);
        float mx = -CUDART_INF_F;
        if (r < n1) {
            const float* row = simb + r * SSTR;
            for (int c4 = c4s; c4 < c4x; c4++) {
                float4 v = *(const float4*)(row + c4 * 4);
                mx = fmaxf(mx, fmaxf(fmaxf(v.x, v.y), fmaxf(v.z, v.w)));
            }
            if (own_tail)
                for (int c = nf << 2; c < n2; c++) mx = fmaxf(mx, row[c]);
        }
        mx = fmaxf(mx, __shfl_xor_sync(0xffffffffu, mx, 1));
        mx = fmaxf(mx, __shfl_xor_sync(0xffffffffu, mx, 2));
        float s = 0.f;
        if (r < n1) {
            const float* row = simb + r * SSTR;
            for (int c4 = c4s; c4 < c4x; c4++) {
                float4 v = *(const float4*)(row + c4 * 4);
                s += __expf(v.x - mx) + __expf(v.y - mx) + __expf(v.z - mx) + __expf(v.w - mx);
            }
            if (own_tail)
                for (int c = nf << 2; c < n2; c++) s += __expf(row[c] - mx);
        }
        s += __shfl_xor_sync(0xffffffffu, s, 1);
        s += __shfl_xor_sync(0xffffffffu, s, 2);
        if (h == 0) {
            if (r < n1) { rowmax[r] = mx; rowinv[r] = 1.f / s; am[r] = __expf(mx) * s; }
            else        { rowmax[r] = 0.f; rowinv[r] = 0.f; am[r] = 0.f; }
        }
    } else {
        int c = (tid - 512) >> 2, h = tid & 3;
        int rs = h * 32, re = min(n1, rs + 32);
        float mx = -CUDART_INF_F;
        if (c < n2) for (int r = rs; r < re; r++) mx = fmaxf(mx, simb[r * SSTR + c]);
        mx = fmaxf(mx, __shfl_xor_sync(0xffffffffu, mx, 1));
        mx = fmaxf(mx, __shfl_xor_sync(0xffffffffu, mx, 2));
        float s = 0.f;
        if (c < n2) for (int r = rs; r < re; r++) s += __expf(simb[r * SSTR + c] - mx);
        s += __shfl_xor_sync(0xffffffffu, s, 1);
        s += __shfl_xor_sync(0xffffffffu, s, 2);
        if (h == 0) {
            if (c < n2) { colmax[c] = mx; colinv[c] = 1.f / s; bn[c] = __expf(-mx) / s; }
            else        { colmax[c] = 0.f; colinv[c] = 0.f; bn[c] = 0.f; }
        }
    }
    __syncthreads();

    // ---- materialize: s1/s2 -> gmem; s1 fp32 -> simb; s1 packed planes ----
    {
        const float inv1 = 1.f / (float)(MM - n1);
        const float inv2 = 1.f / (float)(MM - n2);
        for (int it = tid; it < MM * 32; it += NTHREADS) {
            int m = it >> 5, n0 = (it & 31) << 2;
            float4 a, c;
            if (m < n1) {
                float4 v = *(const float4*)(simb + m * SSTR + n0);
                float rm = rowmax[m], ri = rowinv[m];
                float4 cm = *(const float4*)(colmax + n0);
                float4 ci = *(const float4*)(colinv + n0);
                a.x = (n0 + 0 < n2) ? __expf(v.x - rm) * ri : 0.f;
                a.y = (n0 + 1 < n2) ? __expf(v.y - rm) * ri : 0.f;
                a.z = (n0 + 2 < n2) ? __expf(v.z - rm) * ri : 0.f;
                a.w = (n0 + 3 < n2) ? __expf(v.w - rm) * ri : 0.f;
                c.x = (n0 + 0 < n2) ? __expf(v.x - cm.x) * ci.x : 0.f;
                c.y = (n0 + 1 < n2) ? __expf(v.y - cm.y) * ci.y : 0.f;
                c.z = (n0 + 2 < n2) ? __expf(v.z - cm.z) * ci.z : 0.f;
                c.w = (n0 + 3 < n2) ? __expf(v.w - cm.w) * ci.w : 0.f;
            } else {
                a.x = (n0 + 0 < n2) ? 0.f : inv2;
                a.y = (n0 + 1 < n2) ? 0.f : inv2;
                a.z = (n0 + 2 < n2) ? 0.f : inv2;
                a.w = (n0 + 3 < n2) ? 0.f : inv2;
                c.x = (n0 + 0 < n2) ? 0.f : inv1;
                c.y = (n0 + 1 < n2) ? 0.f : inv1;
                c.z = (n0 + 2 < n2) ? 0.f : inv1;
                c.w = (n0 + 3 < n2) ? 0.f : inv1;
            }
            size_t go = (size_t)b * (MM * MM) + (size_t)m * MM + n0;
            *(float4*)(s1_out + go) = a;
            *(float4*)(s2_out + go) = c;
            *(float4*)(simb + m * SSTR + n0) = a;
            uint32_t h0, l0, h1, l1;
            split_pair(a.x, a.y, h0, l0);
            split_pair(a.z, a.w, h1, l1);
            *(uint2*)(S1h + m * S1PS + (n0 >> 1)) = make_uint2(h0, h1);
            *(uint2*)(S1l + m * S1PS + (n0 >> 1)) = make_uint2(l0, l1);
        }
    }
    __syncthreads();

    // ---- attention: 32 jobs (16 qn, 16 cn), each 16 rows x 32 cols ----
    if (w < 16) {
        int mt = w >> 1, nh = w & 1;
        int m0 = mt << 4, db = nh << 5;
        if (m0 < n1) {
            float acc[4][4];
#pragma unroll
            for (int n8 = 0; n8 < 4; n8++) { acc[n8][0] = 0.f; acc[n8][1] = 0.f; acc[n8][2] = 0.f; acc[n8][3] = 0.f; }
            int ks16 = (n2 + 15) >> 4;
            for (int kk = 0; kk < ks16; kk++) {
                int k0 = kk << 4;
                int as = (m0 + g) * S1PS + (k0 >> 1) + t;
                int as8 = as + 8 * S1PS;
                uint32_t ah[4] = { S1h[as], S1h[as8], S1h[as + 4], S1h[as8 + 4] };
                uint32_t al[4] = { S1l[as], S1l[as8], S1l[as + 4], S1l[as8 + 4] };
#pragma unroll
                for (int n8 = 0; n8 < 4; n8++) {
                    int nc = db + (n8 << 3) + g;
                    const float* bp = p2 + (k0 + 2 * t) * PSTR + nc;
                    uint32_t bh[2], bl[2];
                    split_pair(bp[0], bp[PSTR], bh[0], bl[0]);
                    split_pair(bp[8 * PSTR], bp[9 * PSTR], bh[1], bl[1]);
                    mma16(acc[n8], ah, bh);
                    mma16(acc[n8], al, bh);
                    mma16(acc[n8], ah, bl);
                }
            }
            int m1 = m0 + g, m2 = m0 + g + 8;
#pragma unroll
            for (int n8 = 0; n8 < 4; n8++) {
                int c = db + (n8 << 3) + 2 * t;
                if (m1 < n1)
                    *(float2*)(res_out + (size_t)(off1 + m1) * DIM + c) = make_float2(acc[n8][0], acc[n8][1]);
                if (m2 < n1)
                    *(float2*)(res_out + (size_t)(off1 + m2) * DIM + c) = make_float2(acc[n8][2], acc[n8][3]);
            }
        }
    } else {
        int nt = (w - 16) >> 1, nh = w & 1;
        int nn0 = nt << 4, db = nh << 5;
        if (nn0 < n2) {
            float acc[4][4];
#pragma unroll
            for (int n8 = 0; n8 < 4; n8++) { acc[n8][0] = 0.f; acc[n8][1] = 0.f; acc[n8][2] = 0.f; acc[n8][3] = 0.f; }
            int ks16 = (n1 + 15) >> 4;
            for (int kk = 0; kk < ks16; kk++) {
                int k0 = kk << 4;
                int kr = k0 + 2 * t;
                float am0 = am[kr], am1 = am[kr + 1], am2 = am[kr + 8], am3 = am[kr + 9];
                const float* s0 = simb + kr * SSTR + nn0 + g;
                const float* s8 = s0 + 8 * SSTR;
                uint32_t ah[4], al[4];
                split_pair(s0[0] * am0, s0[SSTR] * am1, ah[0], al[0]);
                split_pair(s0[8] * am0, s0[SSTR + 8] * am1, ah[1], al[1]);
                split_pair(s8[0] * am2, s8[SSTR] * am3, ah[2], al[2]);
                split_pair(s8[8] * am2, s8[SSTR + 8] * am3, ah[3], al[3]);
#pragma unroll
                for (int n8 = 0; n8 < 4; n8++) {
                    int nc = db + (n8 << 3) + g;
                    const float* bp = p1 + (k0 + 2 * t) * PSTR + nc;
                    uint32_t bh[2], bl[2];
                    split_pair(bp[0], bp[PSTR], bh[0], bl[0]);
                    split_pair(bp[8 * PSTR], bp[9 * PSTR], bh[1], bl[1]);
                    mma16(acc[n8], ah, bh);
                    mma16(acc[n8], al, bh);
                    mma16(acc[n8], ah, bl);
                }
            }
            int r1 = nn0 + g, r2 = nn0 + g + 8;
            float f1 = bn[r1], f2 = bn[r2];
#pragma unroll
            for (int n8 = 0; n8 < 4; n8++) {
                int c = db + (n8 << 3) + 2 * t;
                if (r1 < n2)
                    *(float2*)(res_out + (size_t)(off2 + r1) * DIM + c) =
                        make_float2(acc[n8][0] * f1, acc[n8][1] * f1);
                if (r2 < n2)
                    *(float2*)(res_out + (size_t)(off2 + r2) * DIM + c) =
                        make_float2(acc[n8][2] * f2, acc[n8][3] * f2);
            }
        }
    }
}

extern "C" void kernel_launch(void* const* d_in, const int* in_sizes, int n_in,
                              void* d_out, int out_size) {
    const float* data = (const float*)d_in[0];
    const float* W1   = (const float*)d_in[1];
    const float* b1   = (const float*)d_in[2];
    const float* W2   = (const float*)d_in[3];
    const float* b2   = (const float*)d_in[4];
    const int*   sizes_raw = (const int*)d_in[5];

    float* out = (float*)d_out;
    size_t total_e = (size_t)in_sizes[0];        // total * DIM
    float* s1o = out + total_e;
    float* s2o = s1o + (size_t)NPAIRS * MM * MM;

    cudaFuncSetAttribute(cross_kernel, cudaFuncAttributeMaxDynamicSharedMemorySize, SMEM_BYTES);

    scan_kernel<<<1, 1024>>>(sizes_raw);
    cross_kernel<<<NPAIRS, NTHREADS, SMEM_BYTES>>>(data, W1, b1, W2, b2, out, s1o, s2o);
}